// round 8
// baseline (speedup 1.0000x reference)
#include <cuda_runtime.h>
#include <cuda_fp16.h>
#include <cstdint>

#define BH    64
#define T_LEN 4096
#define D_DIM 128
#define SPLIT 8
#define CHUNK (T_LEN / SPLIT)   // 512
#define KSLAB 32
#define NSLAB (CHUNK / KSLAB)   // 16
#define ASTR  136               // phase-A smem row stride (halves)
#define ABUFB (KSLAB * ASTR * 2)// bytes per phase-A buffer (8704)
#define PAD   136               // phase-B KV smem stride
#define QSTR  40                // phase-B Q slab stride (halves, 80B = 16B-aligned)

// Scratch (static device arrays — no allocs).
__device__ __half g_kvph[SPLIT * BH * D_DIM * D_DIM]; // 16.75 MB fp16 partials
__device__ uint4  g_kvh4[BH * D_DIM * D_DIM / 8];     // 2 MB fp16 KV^T

// ---- helpers ----
__device__ __forceinline__ void mma16816(float* c, const uint32_t* a,
                                         const uint32_t* b) {
    asm volatile(
        "mma.sync.aligned.m16n8k16.row.col.f32.f16.f16.f32 "
        "{%0,%1,%2,%3}, {%4,%5,%6,%7}, {%8,%9}, {%0,%1,%2,%3};"
        : "+f"(c[0]), "+f"(c[1]), "+f"(c[2]), "+f"(c[3])
        : "r"(a[0]), "r"(a[1]), "r"(a[2]), "r"(a[3]), "r"(b[0]), "r"(b[1]));
}
__device__ __forceinline__ void ldsm_x4_t(uint32_t* r, uint32_t addr) {
    asm volatile(
        "ldmatrix.sync.aligned.m8n8.x4.trans.shared.b16 {%0,%1,%2,%3}, [%4];"
        : "=r"(r[0]), "=r"(r[1]), "=r"(r[2]), "=r"(r[3]) : "r"(addr));
}
__device__ __forceinline__ uint32_t smem_u32(const void* p) {
    uint32_t a;
    asm("{ .reg .u64 t; cvta.to.shared.u64 t, %1; cvt.u32.u64 %0, t; }"
        : "=r"(a) : "l"(p));
    return a;
}
__device__ __forceinline__ uint2 cvt4h(float4 f) {
    __half2 h0 = __floats2half2_rn(f.x, f.y);
    __half2 h1 = __floats2half2_rn(f.z, f.w);
    uint2 u;
    u.x = *reinterpret_cast<unsigned int*>(&h0);
    u.y = *reinterpret_cast<unsigned int*>(&h1);
    return u;
}
__device__ __forceinline__ uint32_t cvt2h(float a, float b) {
    __half2 h = __floats2half2_rn(a, b);
    return *reinterpret_cast<unsigned int*>(&h);
}
__device__ __forceinline__ void cp16(uint32_t smem_dst, const void* gsrc) {
    asm volatile("cp.async.cg.shared.global [%0], [%1], 16;"
                 :: "r"(smem_dst), "l"(gsrc) : "memory");
}
#define CP_COMMIT() asm volatile("cp.async.commit_group;" ::: "memory")
#define CP_WAIT0()  asm volatile("cp.async.wait_group 0;" ::: "memory")

// ============================================================================
// Kernel 1: KV^T partials via HMMA, double-buffered smem, fp16 partial out.
// C[e][d] = sum_t V[t][e]*K[t][d]. grid=(SPLIT,BH), block=256 (8 warps 4m x 2n).
// ============================================================================
__global__ __launch_bounds__(256) void kv_hmma(const float* __restrict__ K,
                                               const float* __restrict__ V) {
    __shared__ __half Ks[2][KSLAB * ASTR];
    __shared__ __half Vs[2][KSLAB * ASTR];

    const int tid = threadIdx.x;
    const int bh = blockIdx.y;
    const int t0c = blockIdx.x * CHUNK;
    const float4* Kg4 = (const float4*)(K + (size_t)bh * T_LEN * D_DIM);
    const float4* Vg4 = (const float4*)(V + (size_t)bh * T_LEN * D_DIM);

    const int wid = tid >> 5;
    const int l   = tid & 31;
    const int g   = l >> 2;
    const int q2  = (l & 3) * 2;
    const int wm  = (wid & 3) * 32;     // e origin
    const int wn  = (wid >> 2) * 64;    // d origin

    const uint32_t ks_base = smem_u32(Ks);
    const uint32_t vs_base = smem_u32(Vs);
    const int a_row = (l & 7) + 8 * (l >> 4);
    const int a_col = wm + 8 * ((l >> 3) & 1);
    const int b_row = (l & 7) + 8 * ((l >> 3) & 1);
    const int b_col = wn + 8 * (l >> 4);

    float acc[2][8][4];
    #pragma unroll
    for (int i = 0; i < 2; i++)
        #pragma unroll
        for (int j = 0; j < 8; j++)
            #pragma unroll
            for (int v = 0; v < 4; v++) acc[i][j][v] = 0.f;

    const int st = tid >> 5;            // slab row block helpers
    float4 sk[4], sv[4];
    #pragma unroll
    for (int i = 0; i < 4; i++) {
        int lin = tid + 256 * i;
        int t = lin >> 5, e4 = lin & 31;
        sk[i] = Kg4[(size_t)(t0c + t) * 32 + e4];
        sv[i] = Vg4[(size_t)(t0c + t) * 32 + e4];
    }
    #pragma unroll
    for (int i = 0; i < 4; i++) {
        int lin = tid + 256 * i;
        int t = lin >> 5, e4 = lin & 31;
        *(uint2*)&Ks[0][t * ASTR + e4 * 4] = cvt4h(sk[i]);
        *(uint2*)&Vs[0][t * ASTR + e4 * 4] = cvt4h(sv[i]);
    }
    __syncthreads();

    for (int s = 0; s < NSLAB; s++) {
        const int cur = s & 1;
        // issue next-slab LDGs before compute (latency hidden by MMA loop)
        if (s + 1 < NSLAB) {
            #pragma unroll
            for (int i = 0; i < 4; i++) {
                int lin = tid + 256 * i;
                int t = lin >> 5, e4 = lin & 31;
                sk[i] = Kg4[(size_t)(t0c + (s + 1) * KSLAB + t) * 32 + e4];
                sv[i] = Vg4[(size_t)(t0c + (s + 1) * KSLAB + t) * 32 + e4];
            }
        }

        const uint32_t kb = ks_base + cur * ABUFB;
        const uint32_t vb = vs_base + cur * ABUFB;
        #pragma unroll
        for (int k0 = 0; k0 < KSLAB; k0 += 16) {
            uint32_t af[2][4];
            #pragma unroll
            for (int mi = 0; mi < 2; mi++)
                ldsm_x4_t(af[mi], vb + ((k0 + a_row) * ASTR + a_col + 16 * mi) * 2);
            uint32_t bf[4][4];
            #pragma unroll
            for (int nj = 0; nj < 4; nj++)
                ldsm_x4_t(bf[nj], kb + ((k0 + b_row) * ASTR + b_col + 16 * nj) * 2);
            #pragma unroll
            for (int mi = 0; mi < 2; mi++)
                #pragma unroll
                for (int ni = 0; ni < 8; ni++)
                    mma16816(acc[mi][ni], af[mi], &bf[ni >> 1][(ni & 1) * 2]);
        }

        // write NEXT slab into the other buffer (no WAR on cur)
        if (s + 1 < NSLAB) {
            const int nxt = (s + 1) & 1;
            #pragma unroll
            for (int i = 0; i < 4; i++) {
                int lin = tid + 256 * i;
                int t = lin >> 5, e4 = lin & 31;
                *(uint2*)&Ks[nxt][t * ASTR + e4 * 4] = cvt4h(sk[i]);
                *(uint2*)&Vs[nxt][t * ASTR + e4 * 4] = cvt4h(sv[i]);
            }
        }
        __syncthreads();
    }
    (void)st;

    // epilogue: fp16 partials
    __half* gp = g_kvph + ((size_t)blockIdx.x * BH + bh) * D_DIM * D_DIM;
    #pragma unroll
    for (int mi = 0; mi < 2; mi++) {
        #pragma unroll
        for (int ni = 0; ni < 8; ni++) {
            int r = wm + mi * 16 + g;
            int c = wn + ni * 8 + q2;
            *(uint32_t*)&gp[r * D_DIM + c]       = cvt2h(acc[mi][ni][0], acc[mi][ni][1]);
            *(uint32_t*)&gp[(r + 8) * D_DIM + c] = cvt2h(acc[mi][ni][2], acc[mi][ni][3]);
        }
    }
}

// ============================================================================
// Kernel 2: reduce SPLIT fp16 partials (fp32 accum) -> fp16 KV^T.
// grid=512, block=256; each thread handles 8 halves.
// ============================================================================
__global__ __launch_bounds__(256) void kv_reduce_h() {
    const int idx = blockIdx.x * 256 + threadIdx.x;       // uint4 index, 131072
    const uint4* p4 = (const uint4*)g_kvph;
    float s[8];
    #pragma unroll
    for (int i = 0; i < 8; i++) s[i] = 0.f;
    #pragma unroll
    for (int p = 0; p < SPLIT; p++) {
        uint4 u = p4[(size_t)p * (BH * D_DIM * D_DIM / 8) + idx];
        const unsigned int w[4] = {u.x, u.y, u.z, u.w};
        #pragma unroll
        for (int j = 0; j < 4; j++) {
            __half2 h = *reinterpret_cast<const __half2*>(&w[j]);
            float2 f = __half22float2(h);
            s[2 * j] += f.x; s[2 * j + 1] += f.y;
        }
    }
    uint4 o;
    o.x = cvt2h(s[0], s[1]); o.y = cvt2h(s[2], s[3]);
    o.z = cvt2h(s[4], s[5]); o.w = cvt2h(s[6], s[7]);
    g_kvh4[idx] = o;
}

// ============================================================================
// Kernel 3: out = Q @ KV via HMMA, k-slab pipelined.
// KV tile via cp.async (pure fp16 copy); Q in 4 double-buffered 32-d slabs.
// grid=(32,64), block=256 (8 warps 4m x 2n).
// ============================================================================
__global__ __launch_bounds__(256, 2) void out_hmma(const float* __restrict__ Q,
                                                   float* __restrict__ out) {
    extern __shared__ __half sm[];
    __half* Qs = sm;                       // [2][128][QSTR]
    __half* Ws = sm + 2 * 128 * QSTR;      // [128][PAD]

    const int tid = threadIdx.x;
    const int bh = blockIdx.y;
    const int t0 = blockIdx.x * 128;
    const float4* Qg4 = (const float4*)(Q + ((size_t)bh * T_LEN + t0) * D_DIM);

    // KV tile: 2048 uint4 via cp.async (overlaps with Q slab-0 LDG+convert)
    {
        const uint4* Bg = g_kvh4 + (size_t)bh * 2048;
        const uint32_t ws_base = smem_u32(Ws);
        #pragma unroll
        for (int u = 0; u < 8; u++) {
            int idx = tid + 256 * u;
            int row = idx >> 4;
            int c8  = idx & 15;
            cp16(ws_base + (row * PAD + c8 * 8) * 2, &Bg[row * 16 + c8]);
        }
        CP_COMMIT();
    }

    // Q slab 0 (d 0..31): 4 float4 per thread
    float4 sq[4];
    #pragma unroll
    for (int i = 0; i < 4; i++) {
        int lin = tid + 256 * i;                 // 1024 float4
        int row = lin >> 3, c4 = lin & 7;
        sq[i] = Qg4[row * 32 + c4];
    }
    #pragma unroll
    for (int i = 0; i < 4; i++) {
        int lin = tid + 256 * i;
        int row = lin >> 3, c4 = lin & 7;
        *(uint2*)&Qs[row * QSTR + c4 * 4] = cvt4h(sq[i]);
    }
    CP_WAIT0();
    __syncthreads();

    const int wid = tid >> 5;
    const int l   = tid & 31;
    const int g   = l >> 2;
    const int q2  = (l & 3) * 2;
    const int wm  = (wid & 3) * 32;
    const int wn  = (wid >> 2) * 64;

    float acc[2][8][4];
    #pragma unroll
    for (int i = 0; i < 2; i++)
        #pragma unroll
        for (int j = 0; j < 8; j++)
            #pragma unroll
            for (int v = 0; v < 4; v++) acc[i][j][v] = 0.f;

    #pragma unroll
    for (int ks = 0; ks < 4; ks++) {
        const int cur = ks & 1;
        if (ks + 1 < 4) {
            #pragma unroll
            for (int i = 0; i < 4; i++) {
                int lin = tid + 256 * i;
                int row = lin >> 3, c4 = lin & 7;
                sq[i] = Qg4[row * 32 + (ks + 1) * 8 + c4];
            }
        }

        const __half* Qb = Qs + cur * 128 * QSTR;
        #pragma unroll
        for (int kl = 0; kl < 32; kl += 16) {
            const int k0 = ks * 32 + kl;         // absolute k for Ws
            uint32_t af[2][4];
            #pragma unroll
            for (int mi = 0; mi < 2; mi++) {
                int r = wm + mi * 16 + g;
                af[mi][0] = *(const uint32_t*)&Qb[r * QSTR + kl + q2];
                af[mi][1] = *(const uint32_t*)&Qb[(r + 8) * QSTR + kl + q2];
                af[mi][2] = *(const uint32_t*)&Qb[r * QSTR + kl + q2 + 8];
                af[mi][3] = *(const uint32_t*)&Qb[(r + 8) * QSTR + kl + q2 + 8];
            }
            #pragma unroll
            for (int ni = 0; ni < 8; ni++) {
                int e = wn + ni * 8 + g;
                uint32_t bf[2];
                bf[0] = *(const uint32_t*)&Ws[e * PAD + k0 + q2];
                bf[1] = *(const uint32_t*)&Ws[e * PAD + k0 + q2 + 8];
                mma16816(acc[0][ni], af[0], bf);
                mma16816(acc[1][ni], af[1], bf);
            }
        }

        if (ks + 1 < 4) {
            const int nxt = (ks + 1) & 1;
            #pragma unroll
            for (int i = 0; i < 4; i++) {
                int lin = tid + 256 * i;
                int row = lin >> 3, c4 = lin & 7;
                *(uint2*)&Qs[nxt * 128 * QSTR + row * QSTR + c4 * 4] = cvt4h(sq[i]);
            }
        }
        __syncthreads();
    }

    float* Ob = out + ((size_t)bh * T_LEN + t0) * D_DIM;
    #pragma unroll
    for (int mi = 0; mi < 2; mi++) {
        #pragma unroll
        for (int ni = 0; ni < 8; ni++) {
            int r = wm + mi * 16 + g;
            int c = wn + ni * 8 + q2;
            *(float2*)&Ob[(size_t)r * D_DIM + c] =
                make_float2(acc[mi][ni][0], acc[mi][ni][1]);
            *(float2*)&Ob[(size_t)(r + 8) * D_DIM + c] =
                make_float2(acc[mi][ni][2], acc[mi][ni][3]);
        }
    }
}

// ============================================================================
extern "C" void kernel_launch(void* const* d_in, const int* in_sizes, int n_in,
                              void* d_out, int out_size) {
    const float* Q = (const float*)d_in[0];
    const float* K = (const float*)d_in[1];
    const float* V = (const float*)d_in[2];
    float* out = (float*)d_out;

    kv_hmma<<<dim3(SPLIT, BH), 256>>>(K, V);
    kv_reduce_h<<<512, 256>>>();

    const int smem = (2 * 128 * QSTR + 128 * PAD) * sizeof(__half);  // 55296 B
    cudaFuncSetAttribute(out_hmma,
                         cudaFuncAttributeMaxDynamicSharedMemorySize, smem);
    out_hmma<<<dim3(T_LEN / 128, BH), 256, smem>>>(Q, out);
}

// round 9
// speedup vs baseline: 1.0421x; 1.0421x over previous
#include <cuda_runtime.h>
#include <cuda_fp16.h>
#include <cstdint>

#define BH    64
#define T_LEN 4096
#define D_DIM 128
#define SPLIT 8
#define CHUNK (T_LEN / SPLIT)   // 512

// ---- phase A staging geometry ----
#define STG_A  16                         // t-rows per stage
#define RING_A 5
#define NSTG_A (CHUNK / STG_A)            // 32
#define ASTR   136                        // fp16 tile row stride (halves)
// dynamic smem layout (bytes)
#define A_KR   0
#define A_VR   (RING_A * STG_A * D_DIM * 4)              // 40960
#define A_KH   (2 * RING_A * STG_A * D_DIM * 4)          // 81920
#define A_VH   (A_KH + 2 * STG_A * ASTR * 2)             // +8704
#define A_TOT  (A_VH + 2 * STG_A * ASTR * 2)             // 99328

// ---- phase B staging geometry ----
#define RING_B 3
#define PAD    136                        // KV fp16 stride (halves)
#define QSTR   36                         // Q fp16 slab stride (halves, 72B 8B-aligned)
#define B_QR   0
#define B_WS   (RING_B * 128 * 32 * 4)                   // 49152
#define B_QH   (B_WS + 128 * PAD * 2)                    // +34816
#define B_TOT  (B_QH + 2 * 128 * QSTR * 2)               // +18432 = 102400

// Scratch (static device arrays — no allocs).
__device__ __half g_kvph[SPLIT * BH * D_DIM * D_DIM]; // 16.75 MB fp16 partials
__device__ uint4  g_kvh4[BH * D_DIM * D_DIM / 8];     // 2 MB fp16 KV^T

// ---- helpers ----
__device__ __forceinline__ void mma16816(float* c, const uint32_t* a,
                                         const uint32_t* b) {
    asm volatile(
        "mma.sync.aligned.m16n8k16.row.col.f32.f16.f16.f32 "
        "{%0,%1,%2,%3}, {%4,%5,%6,%7}, {%8,%9}, {%0,%1,%2,%3};"
        : "+f"(c[0]), "+f"(c[1]), "+f"(c[2]), "+f"(c[3])
        : "r"(a[0]), "r"(a[1]), "r"(a[2]), "r"(a[3]), "r"(b[0]), "r"(b[1]));
}
__device__ __forceinline__ void ldsm_x4_t(uint32_t* r, uint32_t addr) {
    asm volatile(
        "ldmatrix.sync.aligned.m8n8.x4.trans.shared.b16 {%0,%1,%2,%3}, [%4];"
        : "=r"(r[0]), "=r"(r[1]), "=r"(r[2]), "=r"(r[3]) : "r"(addr));
}
__device__ __forceinline__ uint32_t smem_u32(const void* p) {
    uint32_t a;
    asm("{ .reg .u64 t; cvta.to.shared.u64 t, %1; cvt.u32.u64 %0, t; }"
        : "=r"(a) : "l"(p));
    return a;
}
__device__ __forceinline__ uint2 cvt4h(float4 f) {
    __half2 h0 = __floats2half2_rn(f.x, f.y);
    __half2 h1 = __floats2half2_rn(f.z, f.w);
    uint2 u;
    u.x = *reinterpret_cast<unsigned int*>(&h0);
    u.y = *reinterpret_cast<unsigned int*>(&h1);
    return u;
}
__device__ __forceinline__ uint32_t cvt2h(float a, float b) {
    __half2 h = __floats2half2_rn(a, b);
    return *reinterpret_cast<unsigned int*>(&h);
}
__device__ __forceinline__ void cp16(uint32_t smem_dst, const void* gsrc) {
    asm volatile("cp.async.cg.shared.global [%0], [%1], 16;"
                 :: "r"(smem_dst), "l"(gsrc) : "memory");
}
#define CP_COMMIT() asm volatile("cp.async.commit_group;" ::: "memory")

// ============================================================================
// Kernel 1: KV^T partials via HMMA, cp.async 5-deep fp32 ring + fp16 hop.
// C[e][d] = sum_t V[t][e]*K[t][d]. grid=(SPLIT,BH), block=256 (8 warps 4m x 2n).
// ============================================================================
__global__ __launch_bounds__(256, 2) void kv_hmma(const float* __restrict__ K,
                                                  const float* __restrict__ V) {
    extern __shared__ char sma[];
    float*  Kr = (float*)(sma + A_KR);     // [RING_A][16*128] fp32
    float*  Vr = (float*)(sma + A_VR);
    __half* Kh = (__half*)(sma + A_KH);    // [2][16*ASTR] fp16
    __half* Vh = (__half*)(sma + A_VH);

    const int tid = threadIdx.x;
    const int bh = blockIdx.y;
    const int t0c = blockIdx.x * CHUNK;
    const float4* Kg4 = (const float4*)(K + (size_t)bh * T_LEN * D_DIM);
    const float4* Vg4 = (const float4*)(V + (size_t)bh * T_LEN * D_DIM);

    const uint32_t kr_base = smem_u32(Kr);
    const uint32_t vr_base = smem_u32(Vr);
    const uint32_t kh_base = smem_u32(Kh);
    const uint32_t vh_base = smem_u32(Vh);

    const int wid = tid >> 5;
    const int l   = tid & 31;
    const int g   = l >> 2;
    const int q2  = (l & 3) * 2;
    const int wm  = (wid & 3) * 32;     // e origin
    const int wn  = (wid >> 2) * 64;    // d origin
    const int a_row = (l & 7) + 8 * (l >> 4);
    const int a_col = wm + 8 * ((l >> 3) & 1);
    const int b_row = (l & 7) + 8 * ((l >> 3) & 1);
    const int b_col = wn + 8 * (l >> 4);

    float acc[2][8][4];
    #pragma unroll
    for (int i = 0; i < 2; i++)
        #pragma unroll
        for (int j = 0; j < 8; j++)
            #pragma unroll
            for (int v = 0; v < 4; v++) acc[i][j][v] = 0.f;

    // issue stage stg (16 t-rows of K and V) into ring slot stg % RING_A
    auto issue = [&](int stg) {
        if (stg < NSTG_A) {
            const int slot = stg % RING_A;
            const float4* Kgs = Kg4 + (size_t)(t0c + stg * STG_A) * 32;
            const float4* Vgs = Vg4 + (size_t)(t0c + stg * STG_A) * 32;
            #pragma unroll
            for (int i = 0; i < 2; i++) {
                int lin = tid + 256 * i;               // 512 float4 per stage
                cp16(kr_base + (slot * 512 + lin) * 16, &Kgs[lin]);
                cp16(vr_base + (slot * 512 + lin) * 16, &Vgs[lin]);
            }
        }
        CP_COMMIT();
    };

    #pragma unroll
    for (int p = 0; p < RING_A - 1; p++) issue(p);     // 4 stages in flight

    for (int s = 0; s < NSTG_A; s++) {
        asm volatile("cp.async.wait_group %0;" :: "n"(RING_A - 2) : "memory");
        __syncthreads();

        // convert stage slot -> fp16 buffers (buf = s&1)
        const int slot = s % RING_A;
        const int buf = s & 1;
        #pragma unroll
        for (int i = 0; i < 2; i++) {
            int lin = tid + 256 * i;
            int t = lin >> 5, c4 = lin & 31;
            float4 kf = *(const float4*)&Kr[slot * 512 * 4 + lin * 4];
            float4 vf = *(const float4*)&Vr[slot * 512 * 4 + lin * 4];
            *(uint2*)&Kh[buf * STG_A * ASTR + t * ASTR + c4 * 4] = cvt4h(kf);
            *(uint2*)&Vh[buf * STG_A * ASTR + t * ASTR + c4 * 4] = cvt4h(vf);
        }
        issue(s + RING_A - 1);
        __syncthreads();

        // MMA on fp16 buf (one k16 step: stage = 16 t)
        const uint32_t kb = kh_base + buf * STG_A * ASTR * 2;
        const uint32_t vb = vh_base + buf * STG_A * ASTR * 2;
        uint32_t af[2][4];
        #pragma unroll
        for (int mi = 0; mi < 2; mi++)
            ldsm_x4_t(af[mi], vb + (a_row * ASTR + a_col + 16 * mi) * 2);
        uint32_t bf[4][4];
        #pragma unroll
        for (int nj = 0; nj < 4; nj++)
            ldsm_x4_t(bf[nj], kb + (b_row * ASTR + b_col + 16 * nj) * 2);
        #pragma unroll
        for (int mi = 0; mi < 2; mi++)
            #pragma unroll
            for (int ni = 0; ni < 8; ni++)
                mma16816(acc[mi][ni], af[mi], &bf[ni >> 1][(ni & 1) * 2]);
    }

    // epilogue: fp16 partials
    __half* gp = g_kvph + ((size_t)blockIdx.x * BH + bh) * D_DIM * D_DIM;
    #pragma unroll
    for (int mi = 0; mi < 2; mi++) {
        #pragma unroll
        for (int ni = 0; ni < 8; ni++) {
            int r = wm + mi * 16 + g;
            int c = wn + ni * 8 + q2;
            *(uint32_t*)&gp[r * D_DIM + c]       = cvt2h(acc[mi][ni][0], acc[mi][ni][1]);
            *(uint32_t*)&gp[(r + 8) * D_DIM + c] = cvt2h(acc[mi][ni][2], acc[mi][ni][3]);
        }
    }
}

// ============================================================================
// Kernel 2: reduce SPLIT fp16 partials (fp32 accum) -> fp16 KV^T.
// ============================================================================
__global__ __launch_bounds__(256) void kv_reduce_h() {
    const int idx = blockIdx.x * 256 + threadIdx.x;       // uint4 index, 131072
    const uint4* p4 = (const uint4*)g_kvph;
    float s[8];
    #pragma unroll
    for (int i = 0; i < 8; i++) s[i] = 0.f;
    #pragma unroll
    for (int p = 0; p < SPLIT; p++) {
        uint4 u = p4[(size_t)p * (BH * D_DIM * D_DIM / 8) + idx];
        const unsigned int w[4] = {u.x, u.y, u.z, u.w};
        #pragma unroll
        for (int j = 0; j < 4; j++) {
            __half2 h = *reinterpret_cast<const __half2*>(&w[j]);
            float2 f = __half22float2(h);
            s[2 * j] += f.x; s[2 * j + 1] += f.y;
        }
    }
    uint4 o;
    o.x = cvt2h(s[0], s[1]); o.y = cvt2h(s[2], s[3]);
    o.z = cvt2h(s[4], s[5]); o.w = cvt2h(s[6], s[7]);
    g_kvh4[idx] = o;
}

// ============================================================================
// Kernel 3: out = Q @ KV via HMMA, cp.async 3-deep fp32 Q ring + fp16 hop.
// grid=(32,64), block=256 (8 warps 4m x 2n).
// ============================================================================
__global__ __launch_bounds__(256, 2) void out_hmma(const float* __restrict__ Q,
                                                   float* __restrict__ out) {
    extern __shared__ char smb[];
    float*  Qr = (float*)(smb + B_QR);     // [RING_B][128*32] fp32
    __half* Ws = (__half*)(smb + B_WS);    // [128][PAD] fp16 KV^T
    __half* Qh = (__half*)(smb + B_QH);    // [2][128*QSTR] fp16

    const int tid = threadIdx.x;
    const int bh = blockIdx.y;
    const int t0 = blockIdx.x * 128;
    const float4* Qg4 = (const float4*)(Q + ((size_t)bh * T_LEN + t0) * D_DIM);

    const uint32_t qr_base = smem_u32(Qr);
    const uint32_t ws_base = smem_u32(Ws);

    auto issueQ = [&](int stg) {           // 32-d slab stg -> slot stg % RING_B
        if (stg < 4) {
            const int slot = stg % RING_B;
            #pragma unroll
            for (int i = 0; i < 4; i++) {
                int lin = tid + 256 * i;               // 1024 float4 per slab
                int row = lin >> 3, c4 = lin & 7;
                cp16(qr_base + (slot * 1024 + lin) * 16,
                     &Qg4[row * 32 + stg * 8 + c4]);
            }
        }
    };

    // group 0: KV tile + Q slab 0; group 1: Q slab 1
    {
        const uint4* Bg = g_kvh4 + (size_t)bh * 2048;
        #pragma unroll
        for (int u = 0; u < 8; u++) {
            int idx = tid + 256 * u;
            int row = idx >> 4;
            int c8  = idx & 15;
            cp16(ws_base + (row * PAD + c8 * 8) * 2, &Bg[row * 16 + c8]);
        }
        issueQ(0);
        CP_COMMIT();
        issueQ(1);
        CP_COMMIT();
    }

    const int wid = tid >> 5;
    const int l   = tid & 31;
    const int g   = l >> 2;
    const int q2  = (l & 3) * 2;
    const int wm  = (wid & 3) * 32;
    const int wn  = (wid >> 2) * 64;

    float acc[2][8][4];
    #pragma unroll
    for (int i = 0; i < 2; i++)
        #pragma unroll
        for (int j = 0; j < 8; j++)
            #pragma unroll
            for (int v = 0; v < 4; v++) acc[i][j][v] = 0.f;

    #pragma unroll
    for (int ks = 0; ks < 4; ks++) {
        asm volatile("cp.async.wait_group %0;" :: "n"(RING_B - 2) : "memory");
        __syncthreads();

        // convert slab slot -> Qh buf (ks&1)
        const int slot = ks % RING_B;
        const int buf = ks & 1;
        #pragma unroll
        for (int i = 0; i < 4; i++) {
            int lin = tid + 256 * i;
            int row = lin >> 3, c4 = lin & 7;
            float4 f = *(const float4*)&Qr[slot * 4096 + lin * 4];
            *(uint2*)&Qh[buf * 128 * QSTR + row * QSTR + c4 * 4] = cvt4h(f);
        }
        issueQ(ks + RING_B - 1);
        CP_COMMIT();
        __syncthreads();

        const __half* Qb = Qh + buf * 128 * QSTR;
        #pragma unroll
        for (int kl = 0; kl < 32; kl += 16) {
            const int k0 = ks * 32 + kl;
            uint32_t af[2][4];
            #pragma unroll
            for (int mi = 0; mi < 2; mi++) {
                int r = wm + mi * 16 + g;
                af[mi][0] = *(const uint32_t*)&Qb[r * QSTR + kl + q2];
                af[mi][1] = *(const uint32_t*)&Qb[(r + 8) * QSTR + kl + q2];
                af[mi][2] = *(const uint32_t*)&Qb[r * QSTR + kl + q2 + 8];
                af[mi][3] = *(const uint32_t*)&Qb[(r + 8) * QSTR + kl + q2 + 8];
            }
            #pragma unroll
            for (int ni = 0; ni < 8; ni++) {
                int e = wn + ni * 8 + g;
                uint32_t bf[2];
                bf[0] = *(const uint32_t*)&Ws[e * PAD + k0 + q2];
                bf[1] = *(const uint32_t*)&Ws[e * PAD + k0 + q2 + 8];
                mma16816(acc[0][ni], af[0], bf);
                mma16816(acc[1][ni], af[1], bf);
            }
        }
    }

    float* Ob = out + ((size_t)bh * T_LEN + t0) * D_DIM;
    #pragma unroll
    for (int mi = 0; mi < 2; mi++) {
        #pragma unroll
        for (int ni = 0; ni < 8; ni++) {
            int r = wm + mi * 16 + g;
            int c = wn + ni * 8 + q2;
            *(float2*)&Ob[(size_t)r * D_DIM + c] =
                make_float2(acc[mi][ni][0], acc[mi][ni][1]);
            *(float2*)&Ob[(size_t)(r + 8) * D_DIM + c] =
                make_float2(acc[mi][ni][2], acc[mi][ni][3]);
        }
    }
}

// ============================================================================
extern "C" void kernel_launch(void* const* d_in, const int* in_sizes, int n_in,
                              void* d_out, int out_size) {
    const float* Q = (const float*)d_in[0];
    const float* K = (const float*)d_in[1];
    const float* V = (const float*)d_in[2];
    float* out = (float*)d_out;

    cudaFuncSetAttribute(kv_hmma,
                         cudaFuncAttributeMaxDynamicSharedMemorySize, A_TOT);
    kv_hmma<<<dim3(SPLIT, BH), 256, A_TOT>>>(K, V);

    kv_reduce_h<<<512, 256>>>();

    cudaFuncSetAttribute(out_hmma,
                         cudaFuncAttributeMaxDynamicSharedMemorySize, B_TOT);
    out_hmma<<<dim3(T_LEN / 128, BH), 256, B_TOT>>>(Q, out);
}

// round 10
// speedup vs baseline: 1.0829x; 1.0392x over previous
#include <cuda_runtime.h>
#include <cuda_fp16.h>
#include <cstdint>

#define BH    64
#define T_LEN 4096
#define D_DIM 128
#define SPLIT 8
#define CHUNK (T_LEN / SPLIT)   // 512

// ---- phase A staging geometry ----
#define STG_A  16                         // t-rows per stage
#define RING_A 5
#define NSTG_A (CHUNK / STG_A)            // 32
#define ASTR   136                        // fp16 tile row stride (halves)
#define A_KR   0
#define A_VR   (RING_A * STG_A * D_DIM * 4)              // 40960
#define A_KH   (2 * RING_A * STG_A * D_DIM * 4)          // 81920
#define A_VH   (A_KH + 2 * STG_A * ASTR * 2)             // +8704
#define A_TOT  (A_VH + 2 * STG_A * ASTR * 2)             // 99328

// ---- phase B staging geometry ----
#define RING_B 3
#define PAD    136                        // KV fp16 stride (halves)
#define QSTR   36                         // Q fp16 slab stride (halves)
#define B_QR   0
#define B_WS   (RING_B * 128 * 32 * 4)                   // 49152
#define B_QH   (B_WS + 128 * PAD * 2)                    // +34816
#define B_TOT  (B_QH + 2 * 128 * QSTR * 2)               // 102400

#define SM_TOT B_TOT                      // union of role layouts

// ---- grid roles (dispatch order matters: producers first) ----
#define N_A    512                        // A: idx 0..511      (bh = idx>>3)
#define N_R    64                         // R: idx 512..575    (bh = idx-512)
#define N_B    1024                       // B: idx 576..1599   (2 t-tiles each)

// Scratch + flags (static device arrays — no allocs).
__device__ __half g_kvph[SPLIT * BH * D_DIM * D_DIM]; // 16.75 MB fp16 partials
__device__ uint4  g_kvh4[BH * D_DIM * D_DIM / 8];     // 2 MB fp16 KV^T
__device__ int    g_flagA[BH];
__device__ int    g_flagR[BH];

// ---- helpers ----
__device__ __forceinline__ void mma16816(float* c, const uint32_t* a,
                                         const uint32_t* b) {
    asm volatile(
        "mma.sync.aligned.m16n8k16.row.col.f32.f16.f16.f32 "
        "{%0,%1,%2,%3}, {%4,%5,%6,%7}, {%8,%9}, {%0,%1,%2,%3};"
        : "+f"(c[0]), "+f"(c[1]), "+f"(c[2]), "+f"(c[3])
        : "r"(a[0]), "r"(a[1]), "r"(a[2]), "r"(a[3]), "r"(b[0]), "r"(b[1]));
}
__device__ __forceinline__ void ldsm_x4_t(uint32_t* r, uint32_t addr) {
    asm volatile(
        "ldmatrix.sync.aligned.m8n8.x4.trans.shared.b16 {%0,%1,%2,%3}, [%4];"
        : "=r"(r[0]), "=r"(r[1]), "=r"(r[2]), "=r"(r[3]) : "r"(addr));
}
__device__ __forceinline__ uint32_t smem_u32(const void* p) {
    uint32_t a;
    asm("{ .reg .u64 t; cvta.to.shared.u64 t, %1; cvt.u32.u64 %0, t; }"
        : "=r"(a) : "l"(p));
    return a;
}
__device__ __forceinline__ uint2 cvt4h(float4 f) {
    __half2 h0 = __floats2half2_rn(f.x, f.y);
    __half2 h1 = __floats2half2_rn(f.z, f.w);
    uint2 u;
    u.x = *reinterpret_cast<unsigned int*>(&h0);
    u.y = *reinterpret_cast<unsigned int*>(&h1);
    return u;
}
__device__ __forceinline__ uint32_t cvt2h(float a, float b) {
    __half2 h = __floats2half2_rn(a, b);
    return *reinterpret_cast<unsigned int*>(&h);
}
__device__ __forceinline__ void cp16(uint32_t smem_dst, const void* gsrc) {
    asm volatile("cp.async.cg.shared.global [%0], [%1], 16;"
                 :: "r"(smem_dst), "l"(gsrc) : "memory");
}
#define CP_COMMIT() asm volatile("cp.async.commit_group;" ::: "memory")

// ============================================================================
// Role A: KV^T partials via HMMA (cp.async 5-deep fp32 ring + fp16 hop).
// ============================================================================
__device__ void role_A(int cta, const float* __restrict__ K,
                       const float* __restrict__ V, char* sma) {
    float*  Kr = (float*)(sma + A_KR);
    float*  Vr = (float*)(sma + A_VR);
    __half* Kh = (__half*)(sma + A_KH);
    __half* Vh = (__half*)(sma + A_VH);

    const int tid = threadIdx.x;
    const int bh = cta >> 3;
    const int split = cta & 7;
    const int t0c = split * CHUNK;
    const float4* Kg4 = (const float4*)(K + (size_t)bh * T_LEN * D_DIM);
    const float4* Vg4 = (const float4*)(V + (size_t)bh * T_LEN * D_DIM);

    const uint32_t kr_base = smem_u32(Kr);
    const uint32_t vr_base = smem_u32(Vr);
    const uint32_t kh_base = smem_u32(Kh);
    const uint32_t vh_base = smem_u32(Vh);

    const int wid = tid >> 5;
    const int l   = tid & 31;
    const int g   = l >> 2;
    const int q2  = (l & 3) * 2;
    const int wm  = (wid & 3) * 32;
    const int wn  = (wid >> 2) * 64;
    const int a_row = (l & 7) + 8 * (l >> 4);
    const int a_col = wm + 8 * ((l >> 3) & 1);
    const int b_row = (l & 7) + 8 * ((l >> 3) & 1);
    const int b_col = wn + 8 * (l >> 4);

    float acc[2][8][4];
    #pragma unroll
    for (int i = 0; i < 2; i++)
        #pragma unroll
        for (int j = 0; j < 8; j++)
            #pragma unroll
            for (int v = 0; v < 4; v++) acc[i][j][v] = 0.f;

    auto issue = [&](int stg) {
        if (stg < NSTG_A) {
            const int slot = stg % RING_A;
            const float4* Kgs = Kg4 + (size_t)(t0c + stg * STG_A) * 32;
            const float4* Vgs = Vg4 + (size_t)(t0c + stg * STG_A) * 32;
            #pragma unroll
            for (int i = 0; i < 2; i++) {
                int lin = tid + 256 * i;
                cp16(kr_base + (slot * 512 + lin) * 16, &Kgs[lin]);
                cp16(vr_base + (slot * 512 + lin) * 16, &Vgs[lin]);
            }
        }
        CP_COMMIT();
    };

    #pragma unroll
    for (int p = 0; p < RING_A - 1; p++) issue(p);

    for (int s = 0; s < NSTG_A; s++) {
        asm volatile("cp.async.wait_group %0;" :: "n"(RING_A - 2) : "memory");
        __syncthreads();

        const int slot = s % RING_A;
        const int buf = s & 1;
        #pragma unroll
        for (int i = 0; i < 2; i++) {
            int lin = tid + 256 * i;
            int t = lin >> 5, c4 = lin & 31;
            float4 kf = *(const float4*)&Kr[slot * 512 * 4 + lin * 4];
            float4 vf = *(const float4*)&Vr[slot * 512 * 4 + lin * 4];
            *(uint2*)&Kh[buf * STG_A * ASTR + t * ASTR + c4 * 4] = cvt4h(kf);
            *(uint2*)&Vh[buf * STG_A * ASTR + t * ASTR + c4 * 4] = cvt4h(vf);
        }
        issue(s + RING_A - 1);
        __syncthreads();

        const uint32_t kb = kh_base + buf * STG_A * ASTR * 2;
        const uint32_t vb = vh_base + buf * STG_A * ASTR * 2;
        uint32_t af[2][4];
        #pragma unroll
        for (int mi = 0; mi < 2; mi++)
            ldsm_x4_t(af[mi], vb + (a_row * ASTR + a_col + 16 * mi) * 2);
        uint32_t bf[4][4];
        #pragma unroll
        for (int nj = 0; nj < 4; nj++)
            ldsm_x4_t(bf[nj], kb + (b_row * ASTR + b_col + 16 * nj) * 2);
        #pragma unroll
        for (int mi = 0; mi < 2; mi++)
            #pragma unroll
            for (int ni = 0; ni < 8; ni++)
                mma16816(acc[mi][ni], af[mi], &bf[ni >> 1][(ni & 1) * 2]);
    }

    __half* gp = g_kvph + ((size_t)split * BH + bh) * D_DIM * D_DIM;
    #pragma unroll
    for (int mi = 0; mi < 2; mi++) {
        #pragma unroll
        for (int ni = 0; ni < 8; ni++) {
            int r = wm + mi * 16 + g;
            int c = wn + ni * 8 + q2;
            *(uint32_t*)&gp[r * D_DIM + c]       = cvt2h(acc[mi][ni][0], acc[mi][ni][1]);
            *(uint32_t*)&gp[(r + 8) * D_DIM + c] = cvt2h(acc[mi][ni][2], acc[mi][ni][3]);
        }
    }

    // release: partials for (split, bh) visible, bump counter
    __syncthreads();
    if (tid == 0) {
        __threadfence();
        atomicAdd(&g_flagA[bh], 1);
    }
}

// ============================================================================
// Role R: per-bh reducer — wait for 8 A-CTAs, reduce partials -> fp16 KV^T.
// ============================================================================
__device__ void role_R(int bh) {
    const int tid = threadIdx.x;
    if (tid == 0)
        while (atomicAdd(&g_flagA[bh], 0) < SPLIT) __nanosleep(200);
    __syncthreads();
    __threadfence();

    const uint4* p4 = (const uint4*)g_kvph;
    #pragma unroll
    for (int i = 0; i < 8; i++) {
        int lin = tid + 256 * i;                  // 2048 uint4 per bh
        float s[8];
        #pragma unroll
        for (int v = 0; v < 8; v++) s[v] = 0.f;
        #pragma unroll
        for (int p = 0; p < SPLIT; p++) {
            uint4 u = p4[((size_t)p * BH + bh) * 2048 + lin];
            const unsigned int w[4] = {u.x, u.y, u.z, u.w};
            #pragma unroll
            for (int j = 0; j < 4; j++) {
                __half2 h = *reinterpret_cast<const __half2*>(&w[j]);
                float2 f = __half22float2(h);
                s[2 * j] += f.x; s[2 * j + 1] += f.y;
            }
        }
        uint4 o;
        o.x = cvt2h(s[0], s[1]); o.y = cvt2h(s[2], s[3]);
        o.z = cvt2h(s[4], s[5]); o.w = cvt2h(s[6], s[7]);
        g_kvh4[(size_t)bh * 2048 + lin] = o;
    }

    __syncthreads();
    if (tid == 0) {
        __threadfence();
        atomicExch(&g_flagR[bh], 1);
    }
}

// ============================================================================
// Role B: out = Q @ KV, 2 t-tiles per CTA (stores overlap next tile's loads).
// ============================================================================
__device__ void role_B(int j, const float* __restrict__ Q,
                       float* __restrict__ out, char* smb) {
    float*  Qr = (float*)(smb + B_QR);
    __half* Ws = (__half*)(smb + B_WS);
    __half* Qh = (__half*)(smb + B_QH);

    const int tid = threadIdx.x;
    const int bh = j >> 4;
    const int pair = j & 15;                 // tiles pair*2, pair*2+1

    if (tid == 0)
        while (atomicAdd(&g_flagR[bh], 0) == 0) __nanosleep(200);
    __syncthreads();

    const uint32_t qr_base = smem_u32(Qr);
    const uint32_t ws_base = smem_u32(Ws);

    const float4* Qt[2];
    Qt[0] = (const float4*)(Q + ((size_t)bh * T_LEN + (pair * 2) * 128) * D_DIM);
    Qt[1] = (const float4*)(Q + ((size_t)bh * T_LEN + (pair * 2 + 1) * 128) * D_DIM);

    auto issueQ = [&](int stg) {             // 8 slabs: tile = stg>>2, d-slab = stg&3
        if (stg < 8) {
            const int slot = stg % RING_B;
            const float4* qb = Qt[stg >> 2];
            const int d8 = (stg & 3) * 8;
            #pragma unroll
            for (int i = 0; i < 4; i++) {
                int lin = tid + 256 * i;
                int row = lin >> 3, c4 = lin & 7;
                cp16(qr_base + (slot * 1024 + lin) * 16, &qb[row * 32 + d8 + c4]);
            }
        }
    };

    {
        const uint4* Bg = g_kvh4 + (size_t)bh * 2048;
        #pragma unroll
        for (int u = 0; u < 8; u++) {
            int idx = tid + 256 * u;
            int row = idx >> 4, c8 = idx & 15;
            cp16(ws_base + (row * PAD + c8 * 8) * 2, &Bg[row * 16 + c8]);
        }
        issueQ(0); CP_COMMIT();
        issueQ(1); CP_COMMIT();
    }

    const int wid = tid >> 5;
    const int l   = tid & 31;
    const int g   = l >> 2;
    const int q2  = (l & 3) * 2;
    const int wm  = (wid & 3) * 32;
    const int wn  = (wid >> 2) * 64;

    float acc[2][8][4];
    #pragma unroll
    for (int i = 0; i < 2; i++)
        #pragma unroll
        for (int jj = 0; jj < 8; jj++)
            #pragma unroll
            for (int v = 0; v < 4; v++) acc[i][jj][v] = 0.f;

    for (int ks = 0; ks < 8; ks++) {
        asm volatile("cp.async.wait_group %0;" :: "n"(RING_B - 2) : "memory");
        __syncthreads();

        const int slot = ks % RING_B;
        const int buf = ks & 1;
        #pragma unroll
        for (int i = 0; i < 4; i++) {
            int lin = tid + 256 * i;
            int row = lin >> 3, c4 = lin & 7;
            float4 f = *(const float4*)&Qr[slot * 4096 + lin * 4];
            *(uint2*)&Qh[buf * 128 * QSTR + row * QSTR + c4 * 4] = cvt4h(f);
        }
        issueQ(ks + 2);
        CP_COMMIT();
        __syncthreads();

        const __half* Qb = Qh + buf * 128 * QSTR;
        const int kbase = (ks & 3) * 32;
        #pragma unroll
        for (int kl = 0; kl < 32; kl += 16) {
            const int k0 = kbase + kl;
            uint32_t af[2][4];
            #pragma unroll
            for (int mi = 0; mi < 2; mi++) {
                int r = wm + mi * 16 + g;
                af[mi][0] = *(const uint32_t*)&Qb[r * QSTR + kl + q2];
                af[mi][1] = *(const uint32_t*)&Qb[(r + 8) * QSTR + kl + q2];
                af[mi][2] = *(const uint32_t*)&Qb[r * QSTR + kl + q2 + 8];
                af[mi][3] = *(const uint32_t*)&Qb[(r + 8) * QSTR + kl + q2 + 8];
            }
            #pragma unroll
            for (int ni = 0; ni < 8; ni++) {
                int e = wn + ni * 8 + g;
                uint32_t bf[2];
                bf[0] = *(const uint32_t*)&Ws[e * PAD + k0 + q2];
                bf[1] = *(const uint32_t*)&Ws[e * PAD + k0 + q2 + 8];
                mma16816(acc[0][ni], af[0], bf);
                mma16816(acc[1][ni], af[1], bf);
            }
        }

        if ((ks & 3) == 3) {                 // tile (ks>>2) complete: store
            float* Ob = out +
                ((size_t)bh * T_LEN + (pair * 2 + (ks >> 2)) * 128) * D_DIM;
            #pragma unroll
            for (int mi = 0; mi < 2; mi++) {
                #pragma unroll
                for (int ni = 0; ni < 8; ni++) {
                    int r = wm + mi * 16 + g;
                    int c = wn + ni * 8 + q2;
                    *(float2*)&Ob[(size_t)r * D_DIM + c] =
                        make_float2(acc[mi][ni][0], acc[mi][ni][1]);
                    *(float2*)&Ob[(size_t)(r + 8) * D_DIM + c] =
                        make_float2(acc[mi][ni][2], acc[mi][ni][3]);
                    #pragma unroll
                    for (int v = 0; v < 4; v++) acc[mi][ni][v] = 0.f;
                }
            }
        }
    }
}

// ============================================================================
__global__ void reset_flags() {
    if (threadIdx.x < BH) {
        g_flagA[threadIdx.x] = 0;
        g_flagR[threadIdx.x] = 0;
    }
}

__global__ __launch_bounds__(256, 2) void fused(const float* __restrict__ Q,
                                                const float* __restrict__ K,
                                                const float* __restrict__ V,
                                                float* __restrict__ out) {
    extern __shared__ char smx[];
    const int cta = blockIdx.x;
    if (cta < N_A) {
        role_A(cta, K, V, smx);
    } else if (cta < N_A + N_R) {
        role_R(cta - N_A);
    } else {
        role_B(cta - N_A - N_R, Q, out, smx);
    }
}

extern "C" void kernel_launch(void* const* d_in, const int* in_sizes, int n_in,
                              void* d_out, int out_size) {
    const float* Q = (const float*)d_in[0];
    const float* K = (const float*)d_in[1];
    const float* V = (const float*)d_in[2];
    float* out = (float*)d_out;

    reset_flags<<<1, 64>>>();

    cudaFuncSetAttribute(fused,
                         cudaFuncAttributeMaxDynamicSharedMemorySize, SM_TOT);
    fused<<<N_A + N_R + N_B, 256, SM_TOT>>>(Q, K, V, out);
}